// round 2
// baseline (speedup 1.0000x reference)
#include <cuda_runtime.h>

// DeltaEncoder: delta -> BatchNorm(1ch, eval) -> Linear(1,64) broadcast ->
// LIF recurrence over the 64 output channels (scan axis is O).
// Output [B, O, F, T] float32 spikes (0/1). B=32, T=512, F=64, O=64.
// 268 MB output => HBM-write-bound. One thread handles 8 consecutive t;
// per o it writes 2x float4 with streaming (evict-first) hint.

#define BB 32
#define TT 512
#define FF 64
#define OO 64

__global__ __launch_bounds__(256)
void delta_encoder_kernel(const float* __restrict__ in,     // [B,T,F]
                          const float* __restrict__ enc_w,  // [O]
                          const float* __restrict__ enc_b,  // [O]
                          const float* __restrict__ bn_w,
                          const float* __restrict__ bn_b,
                          const float* __restrict__ bn_mean,
                          const float* __restrict__ bn_var,
                          float* __restrict__ out)          // [B,O,F,T]
{
    // Stage 0.5*w and 0.5*b so the charge step is 2 FFMAs:
    // h = 0.5*(v + x*w + b) = fmaf(v, 0.5, fmaf(x, 0.5w, 0.5b))
    __shared__ float sw[OO];
    __shared__ float sb[OO];
    int tid = threadIdx.x;
    if (tid < OO) {
        sw[tid] = 0.5f * enc_w[tid];
        sb[tid] = 0.5f * enc_b[tid];
    }
    __syncthreads();

    int idx = blockIdx.x * blockDim.x + tid;       // 0 .. B*F*T/8-1
    const int T8 = TT / 8;                         // 64
    int t8 = idx % T8;
    int f  = (idx / T8) % FF;
    int b  = idx / (T8 * FF);
    int t  = t8 * 8;

    // BatchNorm constants (single channel, eval mode)
    float inv  = bn_w[0] * rsqrtf(bn_var[0] + 1e-5f);
    float mean = bn_mean[0];
    float beta = bn_b[0];

    // Load inputs t-1 .. t+7 (stride F floats = 256B in memory)
    const float* ip = in + ((long)b * TT + t) * FF + f;
    float xi[9];
    xi[0] = (t == 0) ? ip[0] : ip[-FF];            // makes delta at t=0 equal 0
    #pragma unroll
    for (int i = 0; i < 8; i++) xi[i + 1] = ip[i * FF];

    float x[8];
    #pragma unroll
    for (int i = 0; i < 8; i++)
        x[i] = ((xi[i + 1] - xi[i]) - mean) * inv + beta;

    float v[8];
    #pragma unroll
    for (int i = 0; i < 8; i++) v[i] = 0.f;

    // out[((b*O + o)*F + f)*T + t], advance o => stride F*T floats
    float* op = out + (((long)b * OO) * FF + f) * (long)TT + t;
    const long strideO = (long)FF * TT;            // floats per o step

    #pragma unroll 4
    for (int o = 0; o < OO; o++) {
        float hw = sw[o];
        float hb = sb[o];

        float h[8], s[8];
        #pragma unroll
        for (int i = 0; i < 8; i++) {
            h[i] = fmaf(v[i], 0.5f, fmaf(x[i], hw, hb));
            bool fire = (h[i] >= 1.0f);
            s[i] = fire ? 1.0f : 0.0f;
            v[i] = fire ? 0.0f : h[i];
        }

        __stcs((float4*)op,       make_float4(s[0], s[1], s[2], s[3]));
        __stcs((float4*)(op + 4), make_float4(s[4], s[5], s[6], s[7]));
        op += strideO;
    }
}

extern "C" void kernel_launch(void* const* d_in, const int* in_sizes, int n_in,
                              void* d_out, int out_size) {
    const float* in      = (const float*)d_in[0];
    const float* enc_w   = (const float*)d_in[1];
    const float* enc_b   = (const float*)d_in[2];
    const float* bn_w    = (const float*)d_in[3];
    const float* bn_b    = (const float*)d_in[4];
    const float* bn_mean = (const float*)d_in[5];
    const float* bn_var  = (const float*)d_in[6];
    float* out = (float*)d_out;

    int total = BB * FF * (TT / 8);       // 131072 threads
    int block = 256;
    int grid  = (total + block - 1) / block;   // 512 blocks
    delta_encoder_kernel<<<grid, block>>>(in, enc_w, enc_b, bn_w, bn_b,
                                          bn_mean, bn_var, out);
}

// round 5
// speedup vs baseline: 1.7352x; 1.7352x over previous
#include <cuda_runtime.h>

// DeltaEncoder: delta -> BatchNorm(1ch, eval) -> Linear(1,64) broadcast ->
// LIF recurrence over the 64 output channels (scan axis is O).
// Output [B, O, F, T] float32 spikes (0/1). B=32, T=512, F=64, O=64.
// 268 MB output => HBM-write-bound. R1 config (best): one thread per
// (b,f,4t), float4 stores, 1024 blocks x 256 threads, plain STG.
// R3 micro-opts: folded 1/tau FFMA, int32 addressing, unroll 8.

#define BB 32
#define TT 512
#define FF 64
#define OO 64

__global__ __launch_bounds__(256)
void delta_encoder_kernel(const float* __restrict__ in,     // [B,T,F]
                          const float* __restrict__ enc_w,  // [O]
                          const float* __restrict__ enc_b,  // [O]
                          const float* __restrict__ bn_w,
                          const float* __restrict__ bn_b,
                          const float* __restrict__ bn_mean,
                          const float* __restrict__ bn_var,
                          float* __restrict__ out)          // [B,O,F,T]
{
    // Stage 0.5*w and 0.5*b: h = 0.5*(v + x*w + b) = fmaf(v,0.5, fmaf(x,hw,hb))
    __shared__ float sw[OO];
    __shared__ float sb[OO];
    int tid = threadIdx.x;
    if (tid < OO) {
        sw[tid] = 0.5f * enc_w[tid];
        sb[tid] = 0.5f * enc_b[tid];
    }
    __syncthreads();

    int idx = blockIdx.x * 256 + tid;              // 0 .. B*F*T/4-1
    const int T4 = TT / 4;                         // 128
    int t4 = idx & (T4 - 1);
    int f  = (idx >> 7) & (FF - 1);
    int b  = idx >> 13;
    int t  = t4 * 4;

    // BatchNorm constants (single channel, eval mode)
    float inv  = bn_w[0] * rsqrtf(bn_var[0] + 1e-5f);
    float mean = bn_mean[0];
    float beta = bn_b[0];

    // Load inputs t-1 .. t+3 (stride F floats = 256B)
    const float* ip = in + (b * TT + t) * FF + f;  // fits in int32
    float xi0 = (t == 0) ? ip[0] : ip[-FF];        // delta at t=0 is 0
    float xi1 = ip[0];
    float xi2 = ip[FF];
    float xi3 = ip[2 * FF];
    float xi4 = ip[3 * FF];

    float x0 = ((xi1 - xi0) - mean) * inv + beta;
    float x1 = ((xi2 - xi1) - mean) * inv + beta;
    float x2 = ((xi3 - xi2) - mean) * inv + beta;
    float x3 = ((xi4 - xi3) - mean) * inv + beta;

    float v0 = 0.f, v1 = 0.f, v2 = 0.f, v3 = 0.f;

    // out[((b*O + o)*F + f)*T + t]; advance o => stride F*T floats = 8192 float4
    float4* op = (float4*)(out + ((b * OO) * FF + f) * TT + t);
    const int strideO4 = FF * TT / 4;              // 8192 float4 per o step

    #pragma unroll 8
    for (int o = 0; o < OO; o++) {
        float hw = sw[o];
        float hb = sb[o];

        float h0 = fmaf(v0, 0.5f, fmaf(x0, hw, hb));
        float h1 = fmaf(v1, 0.5f, fmaf(x1, hw, hb));
        float h2 = fmaf(v2, 0.5f, fmaf(x2, hw, hb));
        float h3 = fmaf(v3, 0.5f, fmaf(x3, hw, hb));

        float s0 = (h0 >= 1.0f) ? 1.0f : 0.0f;
        float s1 = (h1 >= 1.0f) ? 1.0f : 0.0f;
        float s2 = (h2 >= 1.0f) ? 1.0f : 0.0f;
        float s3 = (h3 >= 1.0f) ? 1.0f : 0.0f;

        v0 = (h0 >= 1.0f) ? 0.0f : h0;
        v1 = (h1 >= 1.0f) ? 0.0f : h1;
        v2 = (h2 >= 1.0f) ? 0.0f : h2;
        v3 = (h3 >= 1.0f) ? 0.0f : h3;

        *op = make_float4(s0, s1, s2, s3);
        op += strideO4;
    }
}

extern "C" void kernel_launch(void* const* d_in, const int* in_sizes, int n_in,
                              void* d_out, int out_size) {
    const float* in      = (const float*)d_in[0];
    const float* enc_w   = (const float*)d_in[1];
    const float* enc_b   = (const float*)d_in[2];
    const float* bn_w    = (const float*)d_in[3];
    const float* bn_b    = (const float*)d_in[4];
    const float* bn_mean = (const float*)d_in[5];
    const float* bn_var  = (const float*)d_in[6];
    float* out = (float*)d_out;

    int total = BB * FF * (TT / 4);       // 262144 threads
    int block = 256;
    int grid  = (total + block - 1) / block;   // 1024 blocks
    delta_encoder_kernel<<<grid, block>>>(in, enc_w, enc_b, bn_w, bn_b,
                                          bn_mean, bn_var, out);
}

// round 6
// speedup vs baseline: 1.8520x; 1.0673x over previous
#include <cuda_runtime.h>

// DeltaEncoder: delta -> BatchNorm(1ch eval) -> Linear(1,64) broadcast ->
// LIF recurrence over the 64 output channels. Output [B,O,F,T] f32 (0/1).
// B=32, T=512, F=64, O=64. 268MB output => HBM-write-bound (~5.9TB/s achieved).
// R6: block tile (b, 8f, 128t); input staged through SMEM with coalesced
// loads (4 sectors/warp-load instead of 32), then same o-loop with 512B
// contiguous float4 stores per warp per o.

#define BB 32
#define TT 512
#define FF 64
#define OO 64

__global__ __launch_bounds__(256)
void delta_encoder_kernel(const float* __restrict__ in,     // [B,T,F]
                          const float* __restrict__ enc_w,  // [O]
                          const float* __restrict__ enc_b,  // [O]
                          const float* __restrict__ bn_w,
                          const float* __restrict__ bn_b,
                          const float* __restrict__ bn_mean,
                          const float* __restrict__ bn_var,
                          float* __restrict__ out)          // [B,O,F,T]
{
    // Weights staged with 1/tau folded: h = fmaf(v,0.5, fmaf(x, 0.5w, 0.5b))
    __shared__ float sw[OO];
    __shared__ float sb[OO];
    // Input tile: rows r=0..128 map to t = t0-1 .. t0+127, 8 f columns, pad 9
    __shared__ float sx[129 * 9];

    int tid = threadIdx.x;
    if (tid < OO) {
        sw[tid] = 0.5f * enc_w[tid];
        sb[tid] = 0.5f * enc_b[tid];
    }

    // Decode block: 1024 blocks = 32 b x 8 f-groups x 4 t-quarters
    int bid = blockIdx.x;
    int b  = bid >> 5;
    int fg = (bid >> 2) & 7;
    int tq = bid & 3;
    int f0 = fg * 8;
    int t0 = tq * 128;

    // Cooperative staged load: 1032 floats, consecutive tids read consecutive
    // addresses within each 32B row-chunk (4 sectors per warp-load).
    #pragma unroll
    for (int j = tid; j < 129 * 8; j += 256) {
        int r = j >> 3;
        int c = j & 7;
        int t_g = t0 - 1 + r;
        if (t_g < 0) t_g = 0;            // makes delta at t=0 equal 0
        sx[r * 9 + c] = in[(b * TT + t_g) * FF + f0 + c];
    }
    __syncthreads();

    // BatchNorm constants (single channel, eval mode)
    float inv  = bn_w[0] * rsqrtf(bn_var[0] + 1e-5f);
    float mean = bn_mean[0];
    float beta = bn_b[0];

    int wid  = tid >> 5;      // 0..7 -> f = f0 + wid
    int lane = tid & 31;      // 0..31 -> t = t0 + 4*lane
    int f = f0 + wid;
    int t = t0 + lane * 4;

    // xi[i] = in[b, t-1+i, f] for i=0..4 (row lane*4+i in tile)
    float xi0 = sx[(lane * 4 + 0) * 9 + wid];
    float xi1 = sx[(lane * 4 + 1) * 9 + wid];
    float xi2 = sx[(lane * 4 + 2) * 9 + wid];
    float xi3 = sx[(lane * 4 + 3) * 9 + wid];
    float xi4 = sx[(lane * 4 + 4) * 9 + wid];

    float x0 = ((xi1 - xi0) - mean) * inv + beta;
    float x1 = ((xi2 - xi1) - mean) * inv + beta;
    float x2 = ((xi3 - xi2) - mean) * inv + beta;
    float x3 = ((xi4 - xi3) - mean) * inv + beta;

    float v0 = 0.f, v1 = 0.f, v2 = 0.f, v3 = 0.f;

    // out[((b*O + o)*F + f)*T + t]; o-stride = F*T floats = 8192 float4
    float4* op = (float4*)(out + ((b * OO) * FF + f) * TT + t);
    const int strideO4 = FF * TT / 4;

    #pragma unroll 8
    for (int o = 0; o < OO; o++) {
        float hw = sw[o];
        float hb = sb[o];

        float h0 = fmaf(v0, 0.5f, fmaf(x0, hw, hb));
        float h1 = fmaf(v1, 0.5f, fmaf(x1, hw, hb));
        float h2 = fmaf(v2, 0.5f, fmaf(x2, hw, hb));
        float h3 = fmaf(v3, 0.5f, fmaf(x3, hw, hb));

        float s0 = (h0 >= 1.0f) ? 1.0f : 0.0f;
        float s1 = (h1 >= 1.0f) ? 1.0f : 0.0f;
        float s2 = (h2 >= 1.0f) ? 1.0f : 0.0f;
        float s3 = (h3 >= 1.0f) ? 1.0f : 0.0f;

        v0 = (h0 >= 1.0f) ? 0.0f : h0;
        v1 = (h1 >= 1.0f) ? 0.0f : h1;
        v2 = (h2 >= 1.0f) ? 0.0f : h2;
        v3 = (h3 >= 1.0f) ? 0.0f : h3;

        *op = make_float4(s0, s1, s2, s3);
        op += strideO4;
    }
}

extern "C" void kernel_launch(void* const* d_in, const int* in_sizes, int n_in,
                              void* d_out, int out_size) {
    const float* in      = (const float*)d_in[0];
    const float* enc_w   = (const float*)d_in[1];
    const float* enc_b   = (const float*)d_in[2];
    const float* bn_w    = (const float*)d_in[3];
    const float* bn_b    = (const float*)d_in[4];
    const float* bn_mean = (const float*)d_in[5];
    const float* bn_var  = (const float*)d_in[6];
    float* out = (float*)d_out;

    delta_encoder_kernel<<<1024, 256>>>(in, enc_w, enc_b, bn_w, bn_b,
                                        bn_mean, bn_var, out);
}

// round 8
// speedup vs baseline: 1.9326x; 1.0435x over previous
#include <cuda_runtime.h>

// DeltaEncoder: delta -> BatchNorm(1ch eval) -> Linear(1,64) broadcast ->
// LIF recurrence over the 64 output channels. Output [B,O,F,T] f32 (0/1).
// B=32, T=512, F=64, O=64. 268MB output => HBM-write-bound (~6.4TB/s achieved).
// R7 = R6 (block tile (b, 8f, 128t), SMEM-staged input, float4 stores,
// 1024x256) with ONE change: __stcs (streaming / evict-first) output stores.

#define BB 32
#define TT 512
#define FF 64
#define OO 64

__global__ __launch_bounds__(256)
void delta_encoder_kernel(const float* __restrict__ in,     // [B,T,F]
                          const float* __restrict__ enc_w,  // [O]
                          const float* __restrict__ enc_b,  // [O]
                          const float* __restrict__ bn_w,
                          const float* __restrict__ bn_b,
                          const float* __restrict__ bn_mean,
                          const float* __restrict__ bn_var,
                          float* __restrict__ out)          // [B,O,F,T]
{
    // Weights staged with 1/tau folded: h = fmaf(v,0.5, fmaf(x, 0.5w, 0.5b))
    __shared__ float sw[OO];
    __shared__ float sb[OO];
    // Input tile: rows r=0..128 map to t = t0-1 .. t0+127, 8 f columns, pad 9
    __shared__ float sx[129 * 9];

    int tid = threadIdx.x;
    if (tid < OO) {
        sw[tid] = 0.5f * enc_w[tid];
        sb[tid] = 0.5f * enc_b[tid];
    }

    // Decode block: 1024 blocks = 32 b x 8 f-groups x 4 t-quarters
    int bid = blockIdx.x;
    int b  = bid >> 5;
    int fg = (bid >> 2) & 7;
    int tq = bid & 3;
    int f0 = fg * 8;
    int t0 = tq * 128;

    // Cooperative staged load: 1032 floats, coalesced 32B row-chunks.
    #pragma unroll
    for (int j = tid; j < 129 * 8; j += 256) {
        int r = j >> 3;
        int c = j & 7;
        int t_g = t0 - 1 + r;
        if (t_g < 0) t_g = 0;            // makes delta at t=0 equal 0
        sx[r * 9 + c] = in[(b * TT + t_g) * FF + f0 + c];
    }
    __syncthreads();

    // BatchNorm constants (single channel, eval mode)
    float inv  = bn_w[0] * rsqrtf(bn_var[0] + 1e-5f);
    float mean = bn_mean[0];
    float beta = bn_b[0];

    int wid  = tid >> 5;      // 0..7 -> f = f0 + wid
    int lane = tid & 31;      // 0..31 -> t = t0 + 4*lane
    int f = f0 + wid;
    int t = t0 + lane * 4;

    float xi0 = sx[(lane * 4 + 0) * 9 + wid];
    float xi1 = sx[(lane * 4 + 1) * 9 + wid];
    float xi2 = sx[(lane * 4 + 2) * 9 + wid];
    float xi3 = sx[(lane * 4 + 3) * 9 + wid];
    float xi4 = sx[(lane * 4 + 4) * 9 + wid];

    float x0 = ((xi1 - xi0) - mean) * inv + beta;
    float x1 = ((xi2 - xi1) - mean) * inv + beta;
    float x2 = ((xi3 - xi2) - mean) * inv + beta;
    float x3 = ((xi4 - xi3) - mean) * inv + beta;

    float v0 = 0.f, v1 = 0.f, v2 = 0.f, v3 = 0.f;

    // out[((b*O + o)*F + f)*T + t]; o-stride = F*T floats = 8192 float4
    float4* op = (float4*)(out + ((b * OO) * FF + f) * TT + t);
    const int strideO4 = FF * TT / 4;

    #pragma unroll 8
    for (int o = 0; o < OO; o++) {
        float hw = sw[o];
        float hb = sb[o];

        float h0 = fmaf(v0, 0.5f, fmaf(x0, hw, hb));
        float h1 = fmaf(v1, 0.5f, fmaf(x1, hw, hb));
        float h2 = fmaf(v2, 0.5f, fmaf(x2, hw, hb));
        float h3 = fmaf(v3, 0.5f, fmaf(x3, hw, hb));

        float s0 = (h0 >= 1.0f) ? 1.0f : 0.0f;
        float s1 = (h1 >= 1.0f) ? 1.0f : 0.0f;
        float s2 = (h2 >= 1.0f) ? 1.0f : 0.0f;
        float s3 = (h3 >= 1.0f) ? 1.0f : 0.0f;

        v0 = (h0 >= 1.0f) ? 0.0f : h0;
        v1 = (h1 >= 1.0f) ? 0.0f : h1;
        v2 = (h2 >= 1.0f) ? 0.0f : h2;
        v3 = (h3 >= 1.0f) ? 0.0f : h3;

        __stcs(op, make_float4(s0, s1, s2, s3));
        op += strideO4;
    }
}

extern "C" void kernel_launch(void* const* d_in, const int* in_sizes, int n_in,
                              void* d_out, int out_size) {
    const float* in      = (const float*)d_in[0];
    const float* enc_w   = (const float*)d_in[1];
    const float* enc_b   = (const float*)d_in[2];
    const float* bn_w    = (const float*)d_in[3];
    const float* bn_b    = (const float*)d_in[4];
    const float* bn_mean = (const float*)d_in[5];
    const float* bn_var  = (const float*)d_in[6];
    float* out = (float*)d_out;

    delta_encoder_kernel<<<1024, 256>>>(in, enc_w, enc_b, bn_w, bn_b,
                                        bn_mean, bn_var, out);
}